// round 1
// baseline (speedup 1.0000x reference)
#include <cuda_runtime.h>
#include <cstddef>

#define Bz 32
#define Tt 4096
#define Uu 512
#define Dd 512

// 256MB scratch: holds XW = x@w_x + b_h, overwritten in place by H during scan.
__device__ float g_xw[(size_t)Bz * Tt * Uu];
// per-group monotonic arrival counters (8 groups, padded to 128B apart)
__device__ unsigned int g_ctr[8 * 32];

// ---------------------------------------------------------------------------
// Stable tanh: polynomial near 0, exp-based elsewhere (avoids fast-math traps)
// ---------------------------------------------------------------------------
__device__ __forceinline__ float my_tanh(float x) {
    float ax = fabsf(x);
    if (ax < 0.125f) {
        float x2 = x * x;
        // tanh(x) = x - x^3/3 + 2x^5/15 - ...
        return x * (1.f + x2 * (-0.333333333f + x2 * 0.133333333f));
    }
    float e = __expf(2.f * ax);
    float r = 1.f - 2.f / (1.f + e);
    return copysignf(r, x);
}

// ---------------------------------------------------------------------------
// SGEMM with bias: C[M,512] = A[M,512] @ B[512,512] + bias[512]
// 128x128 tile, BK=16, 256 threads, 8x8 per thread.
// ---------------------------------------------------------------------------
__global__ __launch_bounds__(256) void sgemm_bias(
    const float* __restrict__ A, const float* __restrict__ Bm,
    const float* __restrict__ bias, float* __restrict__ C)
{
    __shared__ float As[16][132];   // transposed A tile, padded (132*4=528, 16B-multiple)
    __shared__ float Bs[16][128];
    const int tid = threadIdx.x;
    const int tx = tid & 15, ty = tid >> 4;
    const size_t row0 = (size_t)blockIdx.y * 128;
    const int col0 = blockIdx.x * 128;

    float acc[8][8];
#pragma unroll
    for (int i = 0; i < 8; i++)
#pragma unroll
        for (int j = 0; j < 8; j++) acc[i][j] = 0.f;

    for (int k0 = 0; k0 < 512; k0 += 16) {
#pragma unroll
        for (int l = 0; l < 2; l++) {
            int f = tid + l * 256;                 // 0..511 (float4 slots)
            int ar = f >> 2, ak = (f & 3) << 2;    // A: 128 rows x 16 k
            float4 av = *(const float4*)&A[(row0 + ar) * 512 + k0 + ak];
            As[ak + 0][ar] = av.x;
            As[ak + 1][ar] = av.y;
            As[ak + 2][ar] = av.z;
            As[ak + 3][ar] = av.w;
            int br = f >> 5, bc = (f & 31) << 2;   // B: 16 rows x 128 cols
            *(float4*)&Bs[br][bc] =
                *(const float4*)&Bm[(size_t)(k0 + br) * 512 + col0 + bc];
        }
        __syncthreads();
#pragma unroll
        for (int k = 0; k < 16; k++) {
            float a[8], b[8];
            *(float4*)&a[0] = *(const float4*)&As[k][ty * 8];
            *(float4*)&a[4] = *(const float4*)&As[k][ty * 8 + 4];
            *(float4*)&b[0] = *(const float4*)&Bs[k][tx * 8];
            *(float4*)&b[4] = *(const float4*)&Bs[k][tx * 8 + 4];
#pragma unroll
            for (int i = 0; i < 8; i++)
#pragma unroll
                for (int j = 0; j < 8; j++)
                    acc[i][j] = fmaf(a[i], b[j], acc[i][j]);
        }
        __syncthreads();
    }

    float bj[8];
    *(float4*)&bj[0] = *(const float4*)&bias[col0 + tx * 8];
    *(float4*)&bj[4] = *(const float4*)&bias[col0 + tx * 8 + 4];
#pragma unroll
    for (int i = 0; i < 8; i++) {
        size_t r = row0 + ty * 8 + i;
        float4 v0 = make_float4(acc[i][0] + bj[0], acc[i][1] + bj[1],
                                acc[i][2] + bj[2], acc[i][3] + bj[3]);
        float4 v1 = make_float4(acc[i][4] + bj[4], acc[i][5] + bj[5],
                                acc[i][6] + bj[6], acc[i][7] + bj[7]);
        *(float4*)&C[r * 512 + col0 + tx * 8] = v0;
        *(float4*)&C[r * 512 + col0 + tx * 8 + 4] = v1;
    }
}

// ---------------------------------------------------------------------------
// Recurrent scan. 8 groups x 16 CTAs. Group g owns batches [4g, 4g+4).
// CTA c-in-group owns output units [32c, 32c+32), w_h slice (512x32) in SMEM.
// h_t written in place over xw in g_xw; per-step group sync via global counter.
// ---------------------------------------------------------------------------
__global__ __launch_bounds__(256) void rnn_scan(const float* __restrict__ w_h,
                                                const float* __restrict__ h0)
{
    extern __shared__ float smem[];
    float* w_s  = smem;                  // 512*32 = 16384 floats (64KB)
    float* h_s  = smem + 16384;          // 4*512  = 2048 floats
    float* psum = smem + 16384 + 2048;   // 8*128  = 1024 floats

    const int tid = threadIdx.x;
    const int grp = blockIdx.x >> 4;     // 0..7
    const int cig = blockIdx.x & 15;     // 0..15
    const int b0 = grp << 2;             // first batch of group
    const int u0 = cig << 5;             // first unit of CTA

    // load w_h slice: w_s[d*32 + j] = w_h[d*512 + u0 + j]
    for (int i = tid; i < 16384; i += 256) {
        int d = i >> 5, j = i & 31;
        w_s[i] = w_h[d * 512 + u0 + j];
    }

    const int ut   = tid & 7;    // which 4-unit tile (units ut*4..ut*4+3)
    const int dcw  = tid >> 3;   // which 16-d chunk (0..31)
    const int lane = tid & 31;
    const int warp = tid >> 5;
    const int d0q  = dcw << 2;   // d-chunk start / 4
    const float4* w_s4 = (const float4*)w_s;   // [d*8 + ut]
    const float4* h_s4 = (const float4*)h_s;   // [b*128 + d4]
    unsigned int* ctr = &g_ctr[grp * 32];

    __syncthreads();

    for (int t = 0; t < Tt; t++) {
        // ---- load h_{t-1} into SMEM (4 batches x 512) ----
        if (t == 0) {
            for (int i = tid; i < 2048; i += 256) h_s[i] = h0[i & 511];
        } else {
            for (int i = tid; i < 512; i += 256) {
                int b = i >> 7, d4 = i & 127;
                ((float4*)h_s)[i] =
                    *((const float4*)&g_xw[((size_t)(b0 + b) * Tt + (t - 1)) * Uu] + d4);
            }
        }
        __syncthreads();

        // ---- partial dot products: 4 units x 4 batches over 16 d ----
        float acc[16];
#pragma unroll
        for (int z = 0; z < 16; z++) acc[z] = 0.f;
#pragma unroll
        for (int i = 0; i < 4; i++) {
            float4 hv[4];
            hv[0] = h_s4[d0q + i];
            hv[1] = h_s4[128 + d0q + i];
            hv[2] = h_s4[256 + d0q + i];
            hv[3] = h_s4[384 + d0q + i];
#pragma unroll
            for (int j = 0; j < 4; j++) {
                float4 wv = w_s4[((d0q + i) * 4 + j) * 8 + ut];
                const float w0 = wv.x, w1 = wv.y, w2 = wv.z, w3 = wv.w;
#pragma unroll
                for (int b = 0; b < 4; b++) {
                    float hb = ((const float*)&hv[b])[j];
                    acc[b * 4 + 0] = fmaf(w0, hb, acc[b * 4 + 0]);
                    acc[b * 4 + 1] = fmaf(w1, hb, acc[b * 4 + 1]);
                    acc[b * 4 + 2] = fmaf(w2, hb, acc[b * 4 + 2]);
                    acc[b * 4 + 3] = fmaf(w3, hb, acc[b * 4 + 3]);
                }
            }
        }

        // ---- reduce over the 4 d-chunks within each warp (lane bits 3,4) ----
#pragma unroll
        for (int z = 0; z < 16; z++) {
            acc[z] += __shfl_xor_sync(0xffffffffu, acc[z], 8);
            acc[z] += __shfl_xor_sync(0xffffffffu, acc[z], 16);
        }
        if (lane < 8) {
#pragma unroll
            for (int uj = 0; uj < 4; uj++)
#pragma unroll
                for (int b = 0; b < 4; b++)
                    psum[warp * 128 + ((ut * 4 + uj) << 2) + b] = acc[b * 4 + uj];
        }
        __syncthreads();

        // ---- final reduce over 8 warps, tanh, write h_t in place over xw ----
        if (tid < 128) {
            float s = 0.f;
#pragma unroll
            for (int w = 0; w < 8; w++) s += psum[w * 128 + tid];
            int ul = tid >> 2, b = tid & 3;
            size_t idx = ((size_t)(b0 + b) * Tt + t) * Uu + u0 + ul;
            g_xw[idx] = my_tanh(s + g_xw[idx]);
        }
        __syncthreads();

        // ---- group barrier: release our stores, wait for the 16 CTAs ----
        if (tid == 0) {
            __threadfence();
            atomicAdd(ctr, 1u);
            unsigned int target = (unsigned int)(16 * (t + 1));
            unsigned int v;
            do {
                asm volatile("ld.global.acquire.gpu.u32 %0, [%1];"
                             : "=r"(v) : "l"(ctr));
            } while (v < target);
        }
        __syncthreads();
    }
}

// ---------------------------------------------------------------------------
__global__ void reset_ctr() { g_ctr[threadIdx.x] = 0u; }

__global__ void copy_hfinal(float* __restrict__ out) {
    int i = blockIdx.x * 256 + threadIdx.x;
    if (i < Bz * Uu) {
        int b = i >> 9, u = i & 511;
        out[(size_t)Bz * Tt * Uu + i] =
            g_xw[((size_t)b * Tt + (Tt - 1)) * Uu + u];
    }
}

// ---------------------------------------------------------------------------
extern "C" void kernel_launch(void* const* d_in, const int* in_sizes, int n_in,
                              void* d_out, int out_size) {
    const float* x   = (const float*)d_in[0];
    const float* w_h = (const float*)d_in[1];
    const float* w_x = (const float*)d_in[2];
    const float* w_y = (const float*)d_in[3];
    const float* b_h = (const float*)d_in[4];
    const float* b_y = (const float*)d_in[5];
    const float* h0  = (const float*)d_in[6];
    float* out = (float*)d_out;

    float* xw = nullptr;
    cudaGetSymbolAddress((void**)&xw, g_xw);
    cudaFuncSetAttribute(rnn_scan, cudaFuncAttributeMaxDynamicSharedMemorySize,
                         (16384 + 2048 + 1024) * 4);

    dim3 gg(4, 1024);  // N-tiles x M-tiles for M=131072, N=512

    // Phase 1: XW = x @ w_x + b_h
    sgemm_bias<<<gg, 256>>>(x, w_x, b_h, xw);
    // Phase 2: sequential scan, H overwrites XW in place
    reset_ctr<<<1, 256>>>();
    rnn_scan<<<128, 256, (16384 + 2048 + 1024) * 4>>>(w_h, h0);
    // Phase 3: Y = H @ w_y + b_y  -> d_out[0 .. B*T*U)
    sgemm_bias<<<gg, 256>>>(xw, w_y, b_y, out);
    // h_final = H[:, T-1, :]      -> d_out[B*T*U ..)
    copy_hfinal<<<64, 256>>>(out);
}